// round 1
// baseline (speedup 1.0000x reference)
#include <cuda_runtime.h>

// Inputs (metadata order, per reference setup_inputs):
//   d_in[0] = q               float32 [50000, 64]   (unused — math cancels)
//   d_in[1] = k               float32 [50000, 64]   (unused)
//   d_in[2] = v               float32 [50000, 64]
//   d_in[3] = self_indices    int32   [800000]
//   d_in[4] = neighbor_indices int32  [800000]      (unused — only enters via
//                                                    scores, which cancel)
// Output: float32 [50000, 64]
//
// Math: out[n] = v[n] * sum_{e: self=n} attn_e  and per-segment attn sums to
// exactly (sum ex)/(sum ex) = 1 when the segment is non-empty, 0 contribution
// when empty. So out[n] = v[n] * has_incoming_edge(n).

#define N_NODES 50000
#define N_EDGES 800000
#define D 64

__device__ int g_flags[N_NODES];

__global__ void zero_flags_kernel() {
    int i = blockIdx.x * blockDim.x + threadIdx.x;
    if (i < N_NODES) g_flags[i] = 0;
}

__global__ void mark_kernel(const int* __restrict__ self_indices) {
    int i = blockIdx.x * blockDim.x + threadIdx.x;
    if (i < N_EDGES) {
        // Duplicate stores of the same value are fine; no atomic needed.
        g_flags[self_indices[i]] = 1;
    }
}

__global__ void gather_kernel(const float4* __restrict__ v4,
                              float4* __restrict__ out4) {
    // N_NODES * D / 4 = 800000 float4 elements; 16 float4 per node.
    int i = blockIdx.x * blockDim.x + threadIdx.x;
    if (i < N_NODES * (D / 4)) {
        int node = i >> 4;  // D/4 == 16
        float4 val;
        if (g_flags[node]) {
            val = v4[i];
        } else {
            val = make_float4(0.f, 0.f, 0.f, 0.f);
        }
        out4[i] = val;
    }
}

extern "C" void kernel_launch(void* const* d_in, const int* in_sizes, int n_in,
                              void* d_out, int out_size) {
    const float* v = (const float*)d_in[2];
    const int* self_indices = (const int*)d_in[3];
    float* out = (float*)d_out;

    zero_flags_kernel<<<(N_NODES + 255) / 256, 256>>>();
    mark_kernel<<<(N_EDGES + 255) / 256, 256>>>(self_indices);
    gather_kernel<<<(N_NODES * (D / 4) + 255) / 256, 256>>>(
        (const float4*)v, (float4*)out);
}